// round 3
// baseline (speedup 1.0000x reference)
#include <cuda_runtime.h>
#include <cstdint>
#include <math_constants.h>

#define TOKENS   32768
#define DIM      2048
#define NE       64
#define TOPK     6

#define BM       128      // tokens per block
#define BK       16       // k-chunk
#define THREADS  128      // 4 warps; warp w owns experts [16w, 16w+16)

#define AK       20       // As row stride (floats): 16 + 4 pad, keeps 16B align + conflict-free phases
#define WSTR     68       // Ws row stride (floats)
#define LSTR     66       // logits row stride (floats), 8B-aligned rows

typedef unsigned long long ull;

// packed f32x2 fma: two fp32 FMAs in one instruction
__device__ __forceinline__ ull fma2(ull a, ull b, ull c) {
    ull d;
    asm("fma.rn.f32x2 %0, %1, %2, %3;" : "=l"(d) : "l"(a), "l"(b), "l"(c));
    return d;
}

// duplicate a scalar into both lanes of an f32x2
__device__ __forceinline__ ull dup2(float v) {
    ull d;
    asm("mov.b64 %0, {%1, %1};" : "=l"(d) : "f"(v));
    return d;
}

__global__ __launch_bounds__(THREADS)
void gate_kernel(const float* __restrict__ x,
                 const float* __restrict__ w,
                 const float* __restrict__ bias,
                 float* __restrict__ out)
{
    // smem overlay:
    //   mainloop: As [BM][AK] (10240B) | Ws [BK][WSTR] (4352B)
    //   epilogue: sLog [BM][LSTR] (33792B) overlays both; sBias after (untouched by mainloop)
    __shared__ __align__(16) unsigned char smem_raw[BM * LSTR * 4 + NE * 4];
    float* As    = reinterpret_cast<float*>(smem_raw);                   // [BM][AK] row-major
    float* Ws    = reinterpret_cast<float*>(smem_raw + BM * AK * 4);     // [BK][WSTR]
    float* sLog  = reinterpret_cast<float*>(smem_raw);                   // [BM][LSTR]
    float* sBias = reinterpret_cast<float*>(smem_raw + BM * LSTR * 4);   // [NE]

    const int tid  = threadIdx.x;
    const int lane = tid & 31;
    const int wid  = tid >> 5;
    const int eg   = wid * 16;          // this warp's expert base (16 experts)
    const int block_m = blockIdx.x * BM;

    if (tid < NE) sBias[tid] = bias[tid];

    const float* xg = x + (size_t)block_m * DIM;

    // acc[token 0..3][expert-pair 0..7]: lane owns tokens lane+32t, experts eg..eg+15
    ull acc[4][8];
    #pragma unroll
    for (int t = 0; t < 4; t++)
        #pragma unroll
        for (int ep = 0; ep < 8; ep++) acc[t][ep] = 0ull;

    // register prefetch buffers
    float4 xr[4];   // 16 floats of x per thread per chunk
    float4 wr[2];   // 8 floats of w per thread per chunk

    // ---- prefetch chunk 0 ----
    #pragma unroll
    for (int i = 0; i < 4; i++) {
        int li = i * THREADS + tid; int tok = li >> 2, dq = li & 3;
        xr[i] = *reinterpret_cast<const float4*>(xg + (size_t)tok * DIM + dq * 4);
    }
    #pragma unroll
    for (int i = 0; i < 2; i++) {
        int li = i * THREADS + tid; int e = li >> 2, dq = li & 3;
        wr[i] = *reinterpret_cast<const float4*>(w + (size_t)e * DIM + dq * 4);
    }

    for (int k0 = 0; k0 < DIM; k0 += BK) {
        // ---- store prefetched regs to smem ----
        // x: row-major, STS.128 (phases conflict-free at stride 20)
        #pragma unroll
        for (int i = 0; i < 4; i++) {
            int li = i * THREADS + tid; int tok = li >> 2, dq = li & 3;
            *reinterpret_cast<float4*>(&As[tok * AK + dq * 4]) = xr[i];
        }
        // w: transposed to [k][expert]
        #pragma unroll
        for (int i = 0; i < 2; i++) {
            int li = i * THREADS + tid; int e = li >> 2, dq = li & 3;
            Ws[(dq * 4 + 0) * WSTR + e] = wr[i].x;
            Ws[(dq * 4 + 1) * WSTR + e] = wr[i].y;
            Ws[(dq * 4 + 2) * WSTR + e] = wr[i].z;
            Ws[(dq * 4 + 3) * WSTR + e] = wr[i].w;
        }
        __syncthreads();

        // ---- prefetch next chunk ----
        int kn = k0 + BK;
        if (kn < DIM) {
            #pragma unroll
            for (int i = 0; i < 4; i++) {
                int li = i * THREADS + tid; int tok = li >> 2, dq = li & 3;
                xr[i] = *reinterpret_cast<const float4*>(xg + (size_t)tok * DIM + kn + dq * 4);
            }
            #pragma unroll
            for (int i = 0; i < 2; i++) {
                int li = i * THREADS + tid; int e = li >> 2, dq = li & 3;
                wr[i] = *reinterpret_cast<const float4*>(w + (size_t)e * DIM + kn + dq * 4);
            }
        }

        // ---- compute: per lane 4 tokens x 16 experts; W reads are warp-uniform broadcasts ----
        #pragma unroll
        for (int g4 = 0; g4 < BK / 4; g4++) {
            // one LDS.128 per token covers 4 k-steps
            float xq[4][4];
            #pragma unroll
            for (int t = 0; t < 4; t++) {
                float4 q = *reinterpret_cast<const float4*>(&As[(lane + 32 * t) * AK + g4 * 4]);
                xq[t][0] = q.x; xq[t][1] = q.y; xq[t][2] = q.z; xq[t][3] = q.w;
            }
            #pragma unroll
            for (int kj = 0; kj < 4; kj++) {
                int kk = g4 * 4 + kj;
                const ulonglong2* wp = reinterpret_cast<const ulonglong2*>(&Ws[kk * WSTR + eg]);
                ulonglong2 wa = wp[0];   // experts eg+0..3  (broadcast)
                ulonglong2 wb = wp[1];   // experts eg+4..7
                ulonglong2 wc = wp[2];   // experts eg+8..11
                ulonglong2 wd = wp[3];   // experts eg+12..15
                ull wv[8] = { wa.x, wa.y, wb.x, wb.y, wc.x, wc.y, wd.x, wd.y };
                #pragma unroll
                for (int t = 0; t < 4; t++) {
                    ull xd = dup2(xq[t][kj]);
                    #pragma unroll
                    for (int ep = 0; ep < 8; ep++)
                        acc[t][ep] = fma2(xd, wv[ep], acc[t][ep]);
                }
            }
        }
        __syncthreads();
    }

    // ---- dump logits: lane's tokens are lane+32t, experts eg..eg+15 ----
    #pragma unroll
    for (int t = 0; t < 4; t++)
        #pragma unroll
        for (int ep = 0; ep < 8; ep++)
            *reinterpret_cast<ull*>(&sLog[(lane + 32 * t) * LSTR + eg + ep * 2]) = acc[t][ep];
    __syncthreads();

    // ---- fused epilogue: 1 thread = 1 token. softmax, +bias select, top-6 ----
    {
        float* row = sLog + tid * LSTR;

        float m = row[0];
        #pragma unroll
        for (int e = 1; e < NE; e++) m = fmaxf(m, row[e]);

        float s = 0.f;
        #pragma unroll
        for (int e = 0; e < NE; e++) { float ex = __expf(row[e] - m); row[e] = ex; s += ex; }
        float inv = 1.0f / s;
        #pragma unroll
        for (int e = 0; e < NE; e++) row[e] *= inv;   // original softmax scores

        const int t = block_m + tid;
        float* outw = out + (size_t)t * TOPK;
        float* outi = out + (size_t)TOKENS * TOPK + (size_t)t * TOPK;

        #pragma unroll
        for (int k = 0; k < TOPK; k++) {
            float best = -CUDART_INF_F; int bi = 0;
            #pragma unroll
            for (int e = 0; e < NE; e++) {
                float b = row[e] + sBias[e];   // bias affects selection only
                if (b > best) { best = b; bi = e; }
            }
            outw[k] = row[bi];                 // ROUTE_SCALE == 1.0
            outi[k] = (float)bi;
            row[bi] = -CUDART_INF_F;
        }
    }
}

extern "C" void kernel_launch(void* const* d_in, const int* in_sizes, int n_in,
                              void* d_out, int out_size)
{
    const float* x    = (const float*)d_in[0];
    const float* w    = (const float*)d_in[1];
    const float* bias = (const float*)d_in[2];
    float* out = (float*)d_out;
    gate_kernel<<<TOKENS / BM, THREADS>>>(x, w, bias, out);
}

// round 4
// speedup vs baseline: 2.0402x; 2.0402x over previous
#include <cuda_runtime.h>
#include <cstdint>
#include <math_constants.h>

#define TOKENS   32768
#define DIM      2048
#define NE       64
#define TOPK     6

#define BM       128      // tokens per block
#define BK       32       // k-chunk
#define THREADS  256      // 8 warps; warp w owns experts [8w, 8w+8)

#define AK       36       // As row stride (floats): 32 + 4 pad -> conflict-free LDS/STS.128
#define WSTR     68       // Ws row stride (floats), 16B-aligned reads
#define LSTR     66       // logits row stride (floats)

typedef unsigned long long ull;

// packed f32x2 fma: two fp32 FMAs in one instruction
__device__ __forceinline__ ull fma2(ull a, ull b, ull c) {
    ull d;
    asm("fma.rn.f32x2 %0, %1, %2, %3;" : "=l"(d) : "l"(a), "l"(b), "l"(c));
    return d;
}

// duplicate a scalar into both lanes of an f32x2 (alu pipe)
__device__ __forceinline__ ull dup2(float v) {
    ull d;
    asm("mov.b64 %0, {%1, %1};" : "=l"(d) : "f"(v));
    return d;
}

__global__ __launch_bounds__(THREADS)
void gate_kernel(const float* __restrict__ x,
                 const float* __restrict__ w,
                 const float* __restrict__ bias,
                 float* __restrict__ out)
{
    // smem overlay:
    //   mainloop: As [BM][AK] (18432B) | Ws [BK][WSTR] (8704B)  = 27136B
    //   epilogue: sLog [BM][LSTR] (33792B) overlays both; sBias after (untouched)
    __shared__ __align__(16) unsigned char smem_raw[BM * LSTR * 4 + NE * 4];
    float* As    = reinterpret_cast<float*>(smem_raw);                   // [BM][AK]
    float* Ws    = reinterpret_cast<float*>(smem_raw + BM * AK * 4);     // [BK][WSTR]
    float* sLog  = reinterpret_cast<float*>(smem_raw);                   // [BM][LSTR]
    float* sBias = reinterpret_cast<float*>(smem_raw + BM * LSTR * 4);   // [NE]

    const int tid  = threadIdx.x;
    const int lane = tid & 31;
    const int wid  = tid >> 5;
    const int eg   = wid * 8;           // this warp's expert base (8 experts)
    const int block_m = blockIdx.x * BM;

    if (tid < NE) sBias[tid] = bias[tid];

    const float* xg = x + (size_t)block_m * DIM;

    // acc[token 0..3][expert-pair 0..3]: lane owns tokens lane+32t, experts eg..eg+7
    ull acc[4][4];
    #pragma unroll
    for (int t = 0; t < 4; t++)
        #pragma unroll
        for (int ep = 0; ep < 4; ep++) acc[t][ep] = 0ull;

    // register prefetch buffers
    float4 xr[4];   // 16 floats of x per thread per chunk (BM*BK/THREADS)
    float4 wr[2];   // 8 floats of w per thread per chunk (NE*BK/THREADS)

    // ---- prefetch chunk 0 ----
    #pragma unroll
    for (int i = 0; i < 4; i++) {
        int li = i * THREADS + tid; int tok = li >> 3, dq = li & 7;
        xr[i] = *reinterpret_cast<const float4*>(xg + (size_t)tok * DIM + dq * 4);
    }
    #pragma unroll
    for (int i = 0; i < 2; i++) {
        int li = i * THREADS + tid; int e = li >> 3, dq = li & 7;
        wr[i] = *reinterpret_cast<const float4*>(w + (size_t)e * DIM + dq * 4);
    }

    for (int k0 = 0; k0 < DIM; k0 += BK) {
        // ---- store prefetched regs to smem ----
        #pragma unroll
        for (int i = 0; i < 4; i++) {
            int li = i * THREADS + tid; int tok = li >> 3, dq = li & 7;
            *reinterpret_cast<float4*>(&As[tok * AK + dq * 4]) = xr[i];
        }
        #pragma unroll
        for (int i = 0; i < 2; i++) {
            int li = i * THREADS + tid; int e = li >> 3, dq = li & 7;
            Ws[(dq * 4 + 0) * WSTR + e] = wr[i].x;
            Ws[(dq * 4 + 1) * WSTR + e] = wr[i].y;
            Ws[(dq * 4 + 2) * WSTR + e] = wr[i].z;
            Ws[(dq * 4 + 3) * WSTR + e] = wr[i].w;
        }
        __syncthreads();

        // ---- prefetch next chunk while computing ----
        int kn = k0 + BK;
        if (kn < DIM) {
            #pragma unroll
            for (int i = 0; i < 4; i++) {
                int li = i * THREADS + tid; int tok = li >> 3, dq = li & 7;
                xr[i] = *reinterpret_cast<const float4*>(xg + (size_t)tok * DIM + kn + dq * 4);
            }
            #pragma unroll
            for (int i = 0; i < 2; i++) {
                int li = i * THREADS + tid; int e = li >> 3, dq = li & 7;
                wr[i] = *reinterpret_cast<const float4*>(w + (size_t)e * DIM + kn + dq * 4);
            }
        }

        // ---- compute: 4 tokens x 8 experts per lane; W reads warp-uniform broadcast ----
        #pragma unroll
        for (int g4 = 0; g4 < BK / 4; g4++) {
            float xq[4][4];
            #pragma unroll
            for (int t = 0; t < 4; t++) {
                float4 q = *reinterpret_cast<const float4*>(&As[(lane + 32 * t) * AK + g4 * 4]);
                xq[t][0] = q.x; xq[t][1] = q.y; xq[t][2] = q.z; xq[t][3] = q.w;
            }
            #pragma unroll
            for (int kj = 0; kj < 4; kj++) {
                int kk = g4 * 4 + kj;
                const ulonglong2* wp = reinterpret_cast<const ulonglong2*>(&Ws[kk * WSTR + eg]);
                ulonglong2 wa = wp[0];   // experts eg+0..3 (broadcast)
                ulonglong2 wb = wp[1];   // experts eg+4..7
                ull wv[4] = { wa.x, wa.y, wb.x, wb.y };
                #pragma unroll
                for (int t = 0; t < 4; t++) {
                    ull xd = dup2(xq[t][kj]);
                    #pragma unroll
                    for (int ep = 0; ep < 4; ep++)
                        acc[t][ep] = fma2(xd, wv[ep], acc[t][ep]);
                }
            }
        }
        __syncthreads();
    }

    // ---- dump logits ----
    #pragma unroll
    for (int t = 0; t < 4; t++)
        #pragma unroll
        for (int ep = 0; ep < 4; ep++)
            *reinterpret_cast<ull*>(&sLog[(lane + 32 * t) * LSTR + eg + ep * 2]) = acc[t][ep];
    __syncthreads();

    // ---- fused epilogue: 1 thread = 1 token ----
    if (tid < BM) {
        float* row = sLog + tid * LSTR;

        float m = row[0];
        #pragma unroll
        for (int e = 1; e < NE; e++) m = fmaxf(m, row[e]);

        float s = 0.f;
        #pragma unroll
        for (int e = 0; e < NE; e++) { float ex = __expf(row[e] - m); row[e] = ex; s += ex; }
        float inv = 1.0f / s;
        #pragma unroll
        for (int e = 0; e < NE; e++) row[e] *= inv;   // original softmax scores

        const int t = block_m + tid;
        float* outw = out + (size_t)t * TOPK;
        float* outi = out + (size_t)TOKENS * TOPK + (size_t)t * TOPK;

        #pragma unroll
        for (int k = 0; k < TOPK; k++) {
            float best = -CUDART_INF_F; int bi = 0;
            #pragma unroll
            for (int e = 0; e < NE; e++) {
                float b = row[e] + sBias[e];   // bias affects selection only
                if (b > best) { best = b; bi = e; }
            }
            outw[k] = row[bi];                 // ROUTE_SCALE == 1.0
            outi[k] = (float)bi;
            row[bi] = -CUDART_INF_F;
        }
    }
}

extern "C" void kernel_launch(void* const* d_in, const int* in_sizes, int n_in,
                              void* d_out, int out_size)
{
    const float* x    = (const float*)d_in[0];
    const float* w    = (const float*)d_in[1];
    const float* bias = (const float*)d_in[2];
    float* out = (float*)d_out;
    gate_kernel<<<TOKENS / BM, THREADS>>>(x, w, bias, out);
}